// round 3
// baseline (speedup 1.0000x reference)
#include <cuda_runtime.h>
#include <math_constants.h>

// Problem shape (fixed by reference setup_inputs)
constexpr int BS  = 128;
constexpr int SEQ = 4096;
constexpr int HID = 128;

constexpr int SPLIT = 8;                         // seq splits per batch
constexpr int ROWS_PER_CTA  = SEQ / SPLIT;       // 512
constexpr int WARPS   = 8;
constexpr int THREADS = WARPS * 32;              // 256
constexpr int ROWS_PER_WARP = ROWS_PER_CTA / WARPS; // 64

// Split-softmax scratch (device globals: no allocation allowed)
__device__ float g_part_m[BS * SPLIT];
__device__ float g_part_l[BS * SPLIT];
__device__ float g_part_acc[BS * SPLIT * HID];

// Pass 1: each CTA handles one (batch, seq-slice). Flash-decode single pass:
// raw scores -> smem (streamed out raw to attn buffer), online-softmax partial
// (m, l, acc[HID]) -> global scratch.
__global__ __launch_bounds__(THREADS, 4)
void attn_pass1(const float* __restrict__ dec,
                const float* __restrict__ enc,
                float* __restrict__ attn_raw)     // [BS, SEQ] raw scores
{
    __shared__ float s_scores[ROWS_PER_CTA];      // 2 KB
    __shared__ float s_m[WARPS];
    __shared__ float s_l[WARPS];
    __shared__ float s_acc[WARPS][HID];           // 4 KB

    const int b    = blockIdx.x;
    const int h    = blockIdx.y;                  // seq slice
    const int tid  = threadIdx.x;
    const int w    = tid >> 5;
    const int lane = tid & 31;

    const float4 d = *reinterpret_cast<const float4*>(dec + (size_t)b * HID + lane * 4);

    const float* enc_b = enc + (size_t)b * SEQ * HID + (size_t)h * ROWS_PER_CTA * HID;

    float m = -CUDART_INF_F;
    float l = 0.0f;
    float4 acc = make_float4(0.f, 0.f, 0.f, 0.f);

    const int row0 = w * ROWS_PER_WARP;
    const int row1 = row0 + ROWS_PER_WARP;

    for (int r = row0; r < row1; r += 4) {
        float4 e0 = *reinterpret_cast<const float4*>(enc_b + (size_t)(r + 0) * HID + lane * 4);
        float4 e1 = *reinterpret_cast<const float4*>(enc_b + (size_t)(r + 1) * HID + lane * 4);
        float4 e2 = *reinterpret_cast<const float4*>(enc_b + (size_t)(r + 2) * HID + lane * 4);
        float4 e3 = *reinterpret_cast<const float4*>(enc_b + (size_t)(r + 3) * HID + lane * 4);

        float sc0 = e0.x * d.x + e0.y * d.y + e0.z * d.z + e0.w * d.w;
        float sc1 = e1.x * d.x + e1.y * d.y + e1.z * d.z + e1.w * d.w;
        float sc2 = e2.x * d.x + e2.y * d.y + e2.z * d.z + e2.w * d.w;
        float sc3 = e3.x * d.x + e3.y * d.y + e3.z * d.z + e3.w * d.w;

        #pragma unroll
        for (int off = 16; off >= 1; off >>= 1) {
            sc0 += __shfl_xor_sync(0xFFFFFFFFu, sc0, off);
            sc1 += __shfl_xor_sync(0xFFFFFFFFu, sc1, off);
            sc2 += __shfl_xor_sync(0xFFFFFFFFu, sc2, off);
            sc3 += __shfl_xor_sync(0xFFFFFFFFu, sc3, off);
        }

        if (lane == 0) {
            s_scores[r + 0] = sc0;
            s_scores[r + 1] = sc1;
            s_scores[r + 2] = sc2;
            s_scores[r + 3] = sc3;
        }

        float mnew = fmaxf(fmaxf(fmaxf(sc0, sc1), fmaxf(sc2, sc3)), m);
        float scale = __expf(m - mnew);           // exp(-inf)=0 on first iter
        float p0 = __expf(sc0 - mnew);
        float p1 = __expf(sc1 - mnew);
        float p2 = __expf(sc2 - mnew);
        float p3 = __expf(sc3 - mnew);
        l = l * scale + (p0 + p1) + (p2 + p3);

        acc.x = acc.x * scale + p0 * e0.x + p1 * e1.x + p2 * e2.x + p3 * e3.x;
        acc.y = acc.y * scale + p0 * e0.y + p1 * e1.y + p2 * e2.y + p3 * e3.y;
        acc.z = acc.z * scale + p0 * e0.z + p1 * e1.z + p2 * e2.z + p3 * e3.z;
        acc.w = acc.w * scale + p0 * e0.w + p1 * e1.w + p2 * e2.w + p3 * e3.w;

        m = mnew;
    }

    if (lane == 0) { s_m[w] = m; s_l[w] = l; }
    *reinterpret_cast<float4*>(&s_acc[w][lane * 4]) = acc;
    __syncthreads();

    // combine warp partials -> CTA partial (redundant per thread, cheap)
    float M = -CUDART_INF_F;
    #pragma unroll
    for (int i = 0; i < WARPS; ++i) M = fmaxf(M, s_m[i]);
    float L = 0.0f;
    #pragma unroll
    for (int i = 0; i < WARPS; ++i) L += s_l[i] * __expf(s_m[i] - M);

    const int part = b * SPLIT + h;
    if (tid == 0) { g_part_m[part] = M; g_part_l[part] = L; }
    if (tid < HID) {
        float c = 0.0f;
        #pragma unroll
        for (int i = 0; i < WARPS; ++i) c += s_acc[i][tid] * __expf(s_m[i] - M);
        g_part_acc[(size_t)part * HID + tid] = c;   // unnormalized, at max M
    }

    // stream raw scores to gmem (coalesced float4); pass 2 normalizes (L2-hot)
    float* out = attn_raw + (size_t)b * SEQ + (size_t)h * ROWS_PER_CTA;
    #pragma unroll
    for (int idx = tid * 2; idx < ROWS_PER_CTA; idx += THREADS * 2) {
        *reinterpret_cast<float2*>(out + idx) =
            *reinterpret_cast<const float2*>(&s_scores[idx]);
    }
}

// Pass 2: grid (BS, 4). Each CTA combines the SPLIT partials (cheap,
// redundant), normalizes its quarter of the attn row (exactly one float4 per
// thread), and the y==0 CTA also writes context.
constexpr int P2_SLICES = 4;
constexpr int P2_THREADS = 256;

__global__ __launch_bounds__(P2_THREADS, 8)
void attn_pass2(float* __restrict__ attn,         // [BS, SEQ] raw in, prob out
                float* __restrict__ ctx)          // [BS, HID]
{
    const int b   = blockIdx.x;
    const int q   = blockIdx.y;                   // quarter of the row
    const int tid = threadIdx.x;

    float pm[SPLIT], pl[SPLIT];
    #pragma unroll
    for (int i = 0; i < SPLIT; ++i) {
        pm[i] = g_part_m[b * SPLIT + i];
        pl[i] = g_part_l[b * SPLIT + i];
    }
    float M = pm[0];
    #pragma unroll
    for (int i = 1; i < SPLIT; ++i) M = fmaxf(M, pm[i]);
    float L = 0.0f;
    #pragma unroll
    for (int i = 0; i < SPLIT; ++i) L += pl[i] * __expf(pm[i] - M);
    const float invL = 1.0f / L;

    if (q == 0 && tid < HID) {
        float c = 0.0f;
        #pragma unroll
        for (int i = 0; i < SPLIT; ++i)
            c += g_part_acc[(size_t)(b * SPLIT + i) * HID + tid] * __expf(pm[i] - M);
        ctx[(size_t)b * HID + tid] = c * invL;
    }

    // exactly one float4 per thread: 256 threads * 4 = 1024 = SEQ/4
    float* a = attn + (size_t)b * SEQ + (size_t)q * (SEQ / P2_SLICES);
    float4 v = *reinterpret_cast<const float4*>(a + tid * 4);
    v.x = __expf(v.x - M) * invL;
    v.y = __expf(v.y - M) * invL;
    v.z = __expf(v.z - M) * invL;
    v.w = __expf(v.w - M) * invL;
    *reinterpret_cast<float4*>(a + tid * 4) = v;
}

extern "C" void kernel_launch(void* const* d_in, const int* in_sizes, int n_in,
                              void* d_out, int out_size)
{
    const float* dec = (const float*)d_in[0];
    const float* enc = (const float*)d_in[1];
    if (n_in >= 2 && in_sizes[0] > in_sizes[1]) {
        dec = (const float*)d_in[1];
        enc = (const float*)d_in[0];
    }

    float* attn = (float*)d_out;                   // [BS, SEQ]
    float* ctx  = attn + (size_t)BS * SEQ;         // [BS, HID]

    attn_pass1<<<dim3(BS, SPLIT), THREADS>>>(dec, enc, attn);
    attn_pass2<<<dim3(BS, P2_SLICES), P2_THREADS>>>(attn, ctx);
}